// round 13
// baseline (speedup 1.0000x reference)
#include <cuda_runtime.h>
#include <cuda_fp16.h>
#include <math.h>
#include <stdint.h>

// Problem constants
#define NB   8192      // B*S tokens (4*2048)
#define DD   1024      // n_embd
#define EE   8         // experts
#define HH   4096      // MLP hidden

// GEMM tiling: CTA 128(M) x 128(N), 8 warps of 64x32, BK=64 halves, 3 stages
#define BM 128
#define BN 128
#define BKH 64                              // halves per stage row (128 B)
#define A_BYTES (BM * BKH * 2)              // 16 KB
#define B_BYTES (BN * BKH * 2)              // 16 KB
#define STAGE_BYTES (A_BYTES + B_BYTES)     // 32 KB
#define NSTAGE 3
#define SMEM_DYN (NSTAGE * STAGE_BYTES)     // 96 KB  -> 2 CTAs/SM

// pre-kernel block partitions: [0,4096) w1-transpose, [4096,8192) w2-transpose,
// [8192, 8192+NB) token work
#define TW1_BLKS 4096
#define TW2_BLKS 4096
#define PRE_TBLKS (TW1_BLKS + TW2_BLKS)

// Scratch (static device globals -- no runtime allocation)
__device__ __half g_h2 [(size_t)NB * DD];   // 16 MB : LN2 output (half)
__device__ __half g_act[(size_t)NB * HH];   // 64 MB : gelu(h2@w1+b1) (half)
__device__ __half g_w1t[(size_t)HH * DD];   // 8 MB  : w1^T (H x D) K-major half
__device__ __half g_w2t[(size_t)DD * HH];   // 8 MB  : w2^T (D x H) K-major half

// ---------------------------------------------------------------------------
// helpers
// ---------------------------------------------------------------------------
__device__ __forceinline__ uint32_t smem_u32(const void* p) {
    uint32_t a;
    asm("{ .reg .u64 t; cvta.to.shared.u64 t, %1; cvt.u32.u64 %0, t; }" : "=r"(a) : "l"(p));
    return a;
}
#define CP_ASYNC16(dst, src) \
    asm volatile("cp.async.cg.shared.global [%0], [%1], 16;" :: "r"(dst), "l"(src))
#define CP_COMMIT() asm volatile("cp.async.commit_group;" ::: "memory")
#define CP_WAIT(n)  asm volatile("cp.async.wait_group %0;" :: "n"(n) : "memory")

#define LDSM4(d0, d1, d2, d3, addr) \
    asm volatile("ldmatrix.sync.aligned.m8n8.x4.shared.b16 {%0,%1,%2,%3}, [%4];" \
        : "=r"(d0), "=r"(d1), "=r"(d2), "=r"(d3) : "r"(addr))

__device__ __forceinline__ void mma16816(float* d, const uint32_t* a, const uint32_t* b) {
    asm volatile(
        "mma.sync.aligned.m16n8k16.row.col.f32.f16.f16.f32 "
        "{%0,%1,%2,%3}, {%4,%5,%6,%7}, {%8,%9}, {%0,%1,%2,%3};"
        : "+f"(d[0]), "+f"(d[1]), "+f"(d[2]), "+f"(d[3])
        : "r"(a[0]), "r"(a[1]), "r"(a[2]), "r"(a[3]), "r"(b[0]), "r"(b[1]));
}

__device__ __forceinline__ float gelu_f(float v) {
    const float c = 0.7978845608028654f;
    float u = c * (v + 0.044715f * v * v * v);
    return 0.5f * v * (1.0f + tanhf(u));
}

// ---------------------------------------------------------------------------
// Stage copy: ROWS rows x 64 halves (128B/row = 8 chunks of 16B), gmem row
// stride ldg halves, XOR-swizzled (chunk c -> c ^ (row & 7)). 256 threads.
// ---------------------------------------------------------------------------
template<int ROWS>
__device__ __forceinline__ void stage_copy(const __half* __restrict__ g, int ldg,
                                           uint32_t sbase, int tid) {
    #pragma unroll
    for (int p = 0; p < ROWS * 8 / 256; p++) {
        const int idx = tid + p * 256;
        const int row = idx >> 3;
        const int c   = idx & 7;
        const uint32_t dst = sbase + (uint32_t)row * 128 + (uint32_t)((c ^ (row & 7)) << 4);
        CP_ASYNC16(dst, (const char*)g + (size_t)row * ldg * 2 + (size_t)c * 16);
    }
}

// ---------------------------------------------------------------------------
// fp16 mma.sync GEMM: 8 warps, warp tile 64(M) x 32(N), arrangement 2Mx4N.
// EPI=1: C(half) = gelu(acc + bias[n])   EPI=2: C(float) += acc
// ---------------------------------------------------------------------------
template<int Kc, int Nc, int EPI>
__global__ __launch_bounds__(256, 2) void mma_gemm(
    const __half* __restrict__ A, const __half* __restrict__ Bt,
    const float* __restrict__ bias, void* __restrict__ Cv)
{
    extern __shared__ __align__(16) char sm[];

    const int tid = threadIdx.x;
    const int wid = tid >> 5;
    const int lid = tid & 31;
    const int q   = lid >> 2;      // 0..7
    const int j   = lid & 3;       // 0..3
    const int m0  = (wid >> 2) * 64;     // 0 or 64
    const int n0  = (wid & 3) * 32;      // 0..96

    const size_t bm = (size_t)blockIdx.y * BM;
    const size_t bn = (size_t)blockIdx.x * BN;
    const __half* Ab = A  + bm * Kc;
    const __half* Bb = Bt + bn * Kc;

    const uint32_t sb0 = smem_u32(sm);
    const int KT = Kc / BKH;

    const int seg = lid >> 3;
    const int rr  = lid & 7;
    const int khA = seg >> 1;
    const int khB = seg & 1;
    uint32_t aAddr[4], bAddr[2];
    #pragma unroll
    for (int mi = 0; mi < 4; mi++)
        aAddr[mi] = (uint32_t)(m0 + mi * 16 + (seg & 1) * 8 + rr) * 128;
    #pragma unroll
    for (int p = 0; p < 2; p++)
        bAddr[p] = (uint32_t)A_BYTES + (uint32_t)(n0 + p * 16 + (seg >> 1) * 8 + rr) * 128;

    float acc[4][4][4];
    #pragma unroll
    for (int mi = 0; mi < 4; mi++)
        #pragma unroll
        for (int ni = 0; ni < 4; ni++)
            #pragma unroll
            for (int v = 0; v < 4; v++) acc[mi][ni][v] = 0.0f;

    #pragma unroll
    for (int s = 0; s < NSTAGE - 1; s++) {
        const uint32_t sa = sb0 + (uint32_t)s * STAGE_BYTES;
        stage_copy<BM>(Ab + (size_t)s * BKH, Kc, sa, tid);
        stage_copy<BN>(Bb + (size_t)s * BKH, Kc, sa + A_BYTES, tid);
        CP_COMMIT();
    }

    for (int kt = 0; kt < KT; kt++) {
        CP_WAIT(NSTAGE - 2);
        __syncthreads();

        if (kt + NSTAGE - 1 < KT) {
            const uint32_t sa = sb0 + (uint32_t)((kt + NSTAGE - 1) % NSTAGE) * STAGE_BYTES;
            stage_copy<BM>(Ab + (size_t)(kt + NSTAGE - 1) * BKH, Kc, sa, tid);
            stage_copy<BN>(Bb + (size_t)(kt + NSTAGE - 1) * BKH, Kc, sa + A_BYTES, tid);
        }
        CP_COMMIT();

        const uint32_t S = sb0 + (uint32_t)(kt % NSTAGE) * STAGE_BYTES;

        #pragma unroll
        for (int ks = 0; ks < BKH / 16; ks++) {
            const uint32_t cA = (uint32_t)(((2 * ks + khA) ^ rr) << 4);
            const uint32_t cB = (uint32_t)(((2 * ks + khB) ^ rr) << 4);

            uint32_t a[4][4];
            #pragma unroll
            for (int mi = 0; mi < 4; mi++)
                LDSM4(a[mi][0], a[mi][1], a[mi][2], a[mi][3], S + aAddr[mi] + cA);

            uint32_t b[2][4];
            #pragma unroll
            for (int p = 0; p < 2; p++)
                LDSM4(b[p][0], b[p][1], b[p][2], b[p][3], S + bAddr[p] + cB);

            #pragma unroll
            for (int mi = 0; mi < 4; mi++)
                #pragma unroll
                for (int ni = 0; ni < 4; ni++) {
                    uint32_t bb[2] = { b[ni >> 1][(ni & 1) * 2],
                                       b[ni >> 1][(ni & 1) * 2 + 1] };
                    mma16816(acc[mi][ni], a[mi], bb);
                }
        }
    }

    // ---- epilogue ----
    const size_t row0 = bm + m0 + q;
    const int    col0 = (int)bn + n0 + 2 * j;

    #pragma unroll
    for (int ni = 0; ni < 4; ni++) {
        const int col = col0 + 8 * ni;
        float bv0 = 0.f, bv1 = 0.f;
        if (EPI == 1) { bv0 = __ldg(bias + col); bv1 = __ldg(bias + col + 1); }
        #pragma unroll
        for (int mi = 0; mi < 4; mi++) {
            const size_t r = row0 + 16 * mi;
            if (EPI == 1) {
                __half* Ch = (__half*)Cv;
                *(half2*)(Ch + r * Nc + col) =
                    __floats2half2_rn(gelu_f(acc[mi][ni][0] + bv0),
                                      gelu_f(acc[mi][ni][1] + bv1));
                *(half2*)(Ch + (r + 8) * Nc + col) =
                    __floats2half2_rn(gelu_f(acc[mi][ni][2] + bv0),
                                      gelu_f(acc[mi][ni][3] + bv1));
            } else {
                float* Cf = (float*)Cv;
                float2 o0 = *(const float2*)(Cf + r * Nc + col);
                float2 o1 = *(const float2*)(Cf + (r + 8) * Nc + col);
                o0.x += acc[mi][ni][0];  o0.y += acc[mi][ni][1];
                o1.x += acc[mi][ni][2];  o1.y += acc[mi][ni][3];
                *(float2*)(Cf + r * Nc + col) = o0;
                *(float2*)(Cf + (r + 8) * Nc + col) = o1;
            }
        }
    }
}

// ---------------------------------------------------------------------------
// Paired block-wide sum over 256 threads: reduces (a,b) together
// ---------------------------------------------------------------------------
__device__ __forceinline__ float2 blk_sum2(float a, float b, float2* sbuf2) {
    #pragma unroll
    for (int o = 16; o > 0; o >>= 1) {
        a += __shfl_xor_sync(0xffffffffu, a, o);
        b += __shfl_xor_sync(0xffffffffu, b, o);
    }
    const int w = threadIdx.x >> 5;
    if ((threadIdx.x & 31) == 0) sbuf2[w] = make_float2(a, b);
    __syncthreads();
    if (threadIdx.x < 32) {
        float xa = 0.f, xb = 0.f;
        if (threadIdx.x < 8) { float2 v = sbuf2[threadIdx.x]; xa = v.x; xb = v.y; }
        #pragma unroll
        for (int o = 4; o > 0; o >>= 1) {
            xa += __shfl_xor_sync(0xffffffffu, xa, o);
            xb += __shfl_xor_sync(0xffffffffu, xb, o);
        }
        if (threadIdx.x == 0) sbuf2[0] = make_float2(xa, xb);
    }
    __syncthreads();
    float2 r = sbuf2[0];
    __syncthreads();
    return r;
}

// ---------------------------------------------------------------------------
// Fused pre-kernel:
//  blocks [0, TW1_BLKS)               : w1 (D x H) -> w1t (H x D) half
//  blocks [TW1_BLKS, PRE_TBLKS)       : w2 (H x D) -> w2t (D x H) half
//  blocks [PRE_TBLKS, PRE_TBLKS+NB)   : per-token LN1 + router + LN2 + gather
// Token path prefetches the 8 LUT float4 loads before the LN work so the
// gather DRAM latency overlaps the reduction chain.
// ---------------------------------------------------------------------------
__global__ __launch_bounds__(256) void pre_kernel(
    const float* __restrict__ x, const int* __restrict__ ids,
    const float* __restrict__ lut,
    const float* __restrict__ ln1g, const float* __restrict__ ln1b,
    const float* __restrict__ ln2g, const float* __restrict__ ln2b,
    const float* __restrict__ rw,  const float* __restrict__ rb,
    const float* __restrict__ bias2,
    const float* __restrict__ w1,  const float* __restrict__ w2,
    float* __restrict__ out)
{
    __shared__ float tile[32][33];          // transpose path
    __shared__ float2 sbuf2[8];             // token path
    __shared__ float rp[EE * 8];
    __shared__ float slog[EE];
    __shared__ float s_h[DD];

    const int bid = blockIdx.x;
    const int tid = threadIdx.x;

    if (bid < PRE_TBLKS) {
        // ---------------- transpose path ----------------
        const float* in;  __half* o;  int rows, cols, bx, by;
        if (bid < TW1_BLKS) {
            in = w1; o = g_w1t; rows = DD; cols = HH;      // grid 128 x 32
            bx = bid & 127;  by = bid >> 7;
        } else {
            const int i2 = bid - TW1_BLKS;
            in = w2; o = g_w2t; rows = HH; cols = DD;      // grid 32 x 128
            bx = i2 & 31;    by = i2 >> 5;
        }
        const int tx = tid & 31, ty = tid >> 5;            // 32 x 8
        int xx = bx * 32 + tx;
        int yy = by * 32 + ty;
        #pragma unroll
        for (int jj = 0; jj < 32; jj += 8)
            tile[ty + jj][tx] = in[(size_t)(yy + jj) * cols + xx];
        __syncthreads();
        xx = by * 32 + tx;
        yy = bx * 32 + ty;
        #pragma unroll
        for (int jj = 0; jj < 32; jj += 8)
            o[(size_t)(yy + jj) * rows + xx] = __float2half(tile[tx][ty + jj]);
        return;
    }

    // ---------------- token path ----------------
    const int t = bid - PRE_TBLKS;

    // prefetch: issue the gather + x loads before any reduction work
    const int sid = __ldg(ids + t);
    const size_t base = (size_t)sid * (size_t)(EE * DD);
    float4 lv[EE];
    #pragma unroll
    for (int e = 0; e < EE; e++)
        lv[e] = ((const float4*)(lut + base + (size_t)e * DD))[tid];
    const float4 xv = ((const float4*)(x + (size_t)t * DD))[tid];

    float s1 = xv.x + xv.y + xv.z + xv.w;
    float s2 = xv.x*xv.x + xv.y*xv.y + xv.z*xv.z + xv.w*xv.w;
    const float2 m1 = blk_sum2(s1, s2, sbuf2);
    const float mu   = m1.x * (1.0f / DD);
    const float var  = m1.y * (1.0f / DD) - mu * mu;
    const float rstd = rsqrtf(var + 1e-5f);

    float4 g1 = ((const float4*)ln1g)[tid];
    float4 c1 = ((const float4*)ln1b)[tid];
    float h[4];
    h[0] = (xv.x - mu) * rstd * g1.x + c1.x;
    h[1] = (xv.y - mu) * rstd * g1.y + c1.y;
    h[2] = (xv.z - mu) * rstd * g1.z + c1.z;
    h[3] = (xv.w - mu) * rstd * g1.w + c1.w;

    // stash h in smem for the coalesced router pass
    ((float4*)s_h)[tid] = make_float4(h[0], h[1], h[2], h[3]);
    __syncthreads();

    // router partials: d = tid + 256*jj -> warp-coalesced rw reads
    float p[EE];
    #pragma unroll
    for (int e = 0; e < EE; e++) p[e] = 0.0f;
    #pragma unroll
    for (int jj = 0; jj < 4; jj++) {
        const int d = tid + 256 * jj;
        const float hd = s_h[d];
        const float4* row = (const float4*)(rw + (size_t)d * EE);
        const float4 r0 = row[0], r1 = row[1];
        p[0] += hd * r0.x;  p[1] += hd * r0.y;
        p[2] += hd * r0.z;  p[3] += hd * r0.w;
        p[4] += hd * r1.x;  p[5] += hd * r1.y;
        p[6] += hd * r1.z;  p[7] += hd * r1.w;
    }
    #pragma unroll
    for (int e = 0; e < EE; e++) {
        float v = p[e];
        #pragma unroll
        for (int o = 16; o > 0; o >>= 1) v += __shfl_xor_sync(0xffffffffu, v, o);
        if ((tid & 31) == 0) rp[e * 8 + (tid >> 5)] = v;
    }
    __syncthreads();
    if (tid < EE) {
        float v = rb[tid];
        #pragma unroll
        for (int w = 0; w < 8; w++) v += rp[tid * 8 + w];
        slog[tid] = v;
    }
    __syncthreads();

    float r[EE];
    float mx = -1e30f;
    #pragma unroll
    for (int e = 0; e < EE; e++) mx = fmaxf(mx, slog[e]);
    float den = 0.0f;
    #pragma unroll
    for (int e = 0; e < EE; e++) { r[e] = __expf(slog[e] - mx); den += r[e]; }
    const float inv = 1.0f / den;
    #pragma unroll
    for (int e = 0; e < EE; e++) r[e] *= inv;

    float t1 = h[0] + h[1] + h[2] + h[3];
    float t2 = h[0]*h[0] + h[1]*h[1] + h[2]*h[2] + h[3]*h[3];
    const float2 m2 = blk_sum2(t1, t2, sbuf2);
    const float mu2   = m2.x * (1.0f / DD);
    const float var2  = m2.y * (1.0f / DD) - mu2 * mu2;
    const float rstd2 = rsqrtf(var2 + 1e-5f);

    float4 g2 = ((const float4*)ln2g)[tid];
    float4 c2 = ((const float4*)ln2b)[tid];
    half2* h2p = (half2*)(g_h2 + (size_t)t * DD);
    h2p[tid * 2]     = __floats2half2_rn((h[0] - mu2) * rstd2 * g2.x + c2.x,
                                         (h[1] - mu2) * rstd2 * g2.y + c2.y);
    h2p[tid * 2 + 1] = __floats2half2_rn((h[2] - mu2) * rstd2 * g2.z + c2.z,
                                         (h[3] - mu2) * rstd2 * g2.w + c2.w);

    // combine prefetched gather values with softmax weights
    float4 acc = make_float4(0.f, 0.f, 0.f, 0.f);
    #pragma unroll
    for (int e = 0; e < EE; e++) {
        acc.x += r[e] * lv[e].x;  acc.y += r[e] * lv[e].y;
        acc.z += r[e] * lv[e].z;  acc.w += r[e] * lv[e].w;
    }

    float4 b2v = ((const float4*)bias2)[tid];
    float4 o;
    o.x = xv.x + acc.x + b2v.x;
    o.y = xv.y + acc.y + b2v.y;
    o.z = xv.z + acc.z + b2v.z;
    o.w = xv.w + acc.w + b2v.w;
    ((float4*)(out + (size_t)t * DD))[tid] = o;
}

// ---------------------------------------------------------------------------
// launch
// ---------------------------------------------------------------------------
extern "C" void kernel_launch(void* const* d_in, const int* in_sizes, int n_in,
                              void* d_out, int out_size)
{
    const float* x    = (const float*)d_in[0];
    const int*   ids  = (const int*)  d_in[1];
    const float* lut  = (const float*)d_in[2];
    const float* ln1g = (const float*)d_in[3];
    const float* ln1b = (const float*)d_in[4];
    const float* ln2g = (const float*)d_in[5];
    const float* ln2b = (const float*)d_in[6];
    const float* rw   = (const float*)d_in[7];
    const float* rb   = (const float*)d_in[8];
    const float* w1   = (const float*)d_in[9];
    const float* b1   = (const float*)d_in[10];
    const float* w2   = (const float*)d_in[11];
    const float* b2   = (const float*)d_in[12];
    float* out = (float*)d_out;

    cudaFuncSetAttribute(mma_gemm<DD, HH, 1>, cudaFuncAttributeMaxDynamicSharedMemorySize, SMEM_DYN);
    cudaFuncSetAttribute(mma_gemm<HH, DD, 2>, cudaFuncAttributeMaxDynamicSharedMemorySize, SMEM_DYN);

    __half* w1t; cudaGetSymbolAddress((void**)&w1t, g_w1t);
    __half* w2t; cudaGetSymbolAddress((void**)&w2t, g_w2t);
    __half* h2;  cudaGetSymbolAddress((void**)&h2,  g_h2);
    __half* act; cudaGetSymbolAddress((void**)&act, g_act);

    // fused: weight transposes + token-wise LN/router/gather (prefetched)
    pre_kernel<<<PRE_TBLKS + NB, 256>>>(
        x, ids, lut, ln1g, ln1b, ln2g, ln2b, rw, rb, b2, w1, w2, out);

    // act = gelu(h2 @ w1 + b1)   [8192 x 4096], K=1024  (half in, half out)
    mma_gemm<DD, HH, 1><<<dim3(HH / BN, NB / BM), 256, SMEM_DYN>>>(h2, w1t, b1, act);

    // out += act @ w2            [8192 x 1024], K=4096  (half in, f32 +=)
    mma_gemm<HH, DD, 2><<<dim3(DD / BN, NB / BM), 256, SMEM_DYN>>>(act, w2t, nullptr, out);
}

// round 14
// speedup vs baseline: 1.0125x; 1.0125x over previous
#include <cuda_runtime.h>
#include <cuda_fp16.h>
#include <math.h>
#include <stdint.h>

// Problem constants
#define NB   8192      // B*S tokens (4*2048)
#define DD   1024      // n_embd
#define EE   8         // experts
#define HH   4096      // MLP hidden

// GEMM tiling: CTA 128(M) x 128(N), 8 warps of 64x32, BK=64 halves, 3 stages
#define BM 128
#define BN 128
#define BKH 64                              // halves per stage row (128 B)
#define A_BYTES (BM * BKH * 2)              // 16 KB
#define B_BYTES (BN * BKH * 2)              // 16 KB
#define STAGE_BYTES (A_BYTES + B_BYTES)     // 32 KB
#define NSTAGE 3
#define SMEM_DYN (NSTAGE * STAGE_BYTES)     // 96 KB  -> 2 CTAs/SM

// pre-kernel block partitions: [0,4096) w1-transpose, [4096,8192) w2-transpose,
// [8192, 8192+NB) token work
#define TW1_BLKS 4096
#define TW2_BLKS 4096
#define PRE_TBLKS (TW1_BLKS + TW2_BLKS)

// Scratch (static device globals -- no runtime allocation)
__device__ __half g_h2 [(size_t)NB * DD];   // 16 MB : LN2 output (half)
__device__ __half g_act[(size_t)NB * HH];   // 64 MB : gelu(h2@w1+b1) (half)
__device__ __half g_w1t[(size_t)HH * DD];   // 8 MB  : w1^T (H x D) K-major half
__device__ __half g_w2t[(size_t)DD * HH];   // 8 MB  : w2^T (D x H) K-major half

// ---------------------------------------------------------------------------
// helpers
// ---------------------------------------------------------------------------
__device__ __forceinline__ uint32_t smem_u32(const void* p) {
    uint32_t a;
    asm("{ .reg .u64 t; cvta.to.shared.u64 t, %1; cvt.u32.u64 %0, t; }" : "=r"(a) : "l"(p));
    return a;
}
#define CP_ASYNC16(dst, src) \
    asm volatile("cp.async.cg.shared.global [%0], [%1], 16;" :: "r"(dst), "l"(src))
#define CP_COMMIT() asm volatile("cp.async.commit_group;" ::: "memory")
#define CP_WAIT(n)  asm volatile("cp.async.wait_group %0;" :: "n"(n) : "memory")

#define LDSM4(d0, d1, d2, d3, addr) \
    asm volatile("ldmatrix.sync.aligned.m8n8.x4.shared.b16 {%0,%1,%2,%3}, [%4];" \
        : "=r"(d0), "=r"(d1), "=r"(d2), "=r"(d3) : "r"(addr))

__device__ __forceinline__ void mma16816(float* d, const uint32_t* a, const uint32_t* b) {
    asm volatile(
        "mma.sync.aligned.m16n8k16.row.col.f32.f16.f16.f32 "
        "{%0,%1,%2,%3}, {%4,%5,%6,%7}, {%8,%9}, {%0,%1,%2,%3};"
        : "+f"(d[0]), "+f"(d[1]), "+f"(d[2]), "+f"(d[3])
        : "r"(a[0]), "r"(a[1]), "r"(a[2]), "r"(a[3]), "r"(b[0]), "r"(b[1]));
}

__device__ __forceinline__ float gelu_f(float v) {
    const float c = 0.7978845608028654f;
    float u = c * (v + 0.044715f * v * v * v);
    return 0.5f * v * (1.0f + tanhf(u));
}

// ---------------------------------------------------------------------------
// Stage copy: ROWS rows x 64 halves (128B/row = 8 chunks of 16B), gmem row
// stride ldg halves, XOR-swizzled (chunk c -> c ^ (row & 7)). 256 threads.
// ---------------------------------------------------------------------------
template<int ROWS>
__device__ __forceinline__ void stage_copy(const __half* __restrict__ g, int ldg,
                                           uint32_t sbase, int tid) {
    #pragma unroll
    for (int p = 0; p < ROWS * 8 / 256; p++) {
        const int idx = tid + p * 256;
        const int row = idx >> 3;
        const int c   = idx & 7;
        const uint32_t dst = sbase + (uint32_t)row * 128 + (uint32_t)((c ^ (row & 7)) << 4);
        CP_ASYNC16(dst, (const char*)g + (size_t)row * ldg * 2 + (size_t)c * 16);
    }
}

// ---------------------------------------------------------------------------
// fp16 mma.sync GEMM: 8 warps, warp tile 64(M) x 32(N), arrangement 2Mx4N.
// EPI=1: C(half) = gelu(acc + bias[n])   EPI=2: C(float) += acc
// ---------------------------------------------------------------------------
template<int Kc, int Nc, int EPI>
__global__ __launch_bounds__(256, 2) void mma_gemm(
    const __half* __restrict__ A, const __half* __restrict__ Bt,
    const float* __restrict__ bias, void* __restrict__ Cv)
{
    extern __shared__ __align__(16) char sm[];

    const int tid = threadIdx.x;
    const int wid = tid >> 5;
    const int lid = tid & 31;
    const int q   = lid >> 2;      // 0..7
    const int j   = lid & 3;       // 0..3
    const int m0  = (wid >> 2) * 64;     // 0 or 64
    const int n0  = (wid & 3) * 32;      // 0..96

    const size_t bm = (size_t)blockIdx.y * BM;
    const size_t bn = (size_t)blockIdx.x * BN;
    const __half* Ab = A  + bm * Kc;
    const __half* Bb = Bt + bn * Kc;

    const uint32_t sb0 = smem_u32(sm);
    const int KT = Kc / BKH;

    const int seg = lid >> 3;
    const int rr  = lid & 7;
    const int khA = seg >> 1;
    const int khB = seg & 1;
    uint32_t aAddr[4], bAddr[2];
    #pragma unroll
    for (int mi = 0; mi < 4; mi++)
        aAddr[mi] = (uint32_t)(m0 + mi * 16 + (seg & 1) * 8 + rr) * 128;
    #pragma unroll
    for (int p = 0; p < 2; p++)
        bAddr[p] = (uint32_t)A_BYTES + (uint32_t)(n0 + p * 16 + (seg >> 1) * 8 + rr) * 128;

    float acc[4][4][4];
    #pragma unroll
    for (int mi = 0; mi < 4; mi++)
        #pragma unroll
        for (int ni = 0; ni < 4; ni++)
            #pragma unroll
            for (int v = 0; v < 4; v++) acc[mi][ni][v] = 0.0f;

    #pragma unroll
    for (int s = 0; s < NSTAGE - 1; s++) {
        const uint32_t sa = sb0 + (uint32_t)s * STAGE_BYTES;
        stage_copy<BM>(Ab + (size_t)s * BKH, Kc, sa, tid);
        stage_copy<BN>(Bb + (size_t)s * BKH, Kc, sa + A_BYTES, tid);
        CP_COMMIT();
    }

    for (int kt = 0; kt < KT; kt++) {
        CP_WAIT(NSTAGE - 2);
        __syncthreads();

        if (kt + NSTAGE - 1 < KT) {
            const uint32_t sa = sb0 + (uint32_t)((kt + NSTAGE - 1) % NSTAGE) * STAGE_BYTES;
            stage_copy<BM>(Ab + (size_t)(kt + NSTAGE - 1) * BKH, Kc, sa, tid);
            stage_copy<BN>(Bb + (size_t)(kt + NSTAGE - 1) * BKH, Kc, sa + A_BYTES, tid);
        }
        CP_COMMIT();

        const uint32_t S = sb0 + (uint32_t)(kt % NSTAGE) * STAGE_BYTES;

        #pragma unroll
        for (int ks = 0; ks < BKH / 16; ks++) {
            const uint32_t cA = (uint32_t)(((2 * ks + khA) ^ rr) << 4);
            const uint32_t cB = (uint32_t)(((2 * ks + khB) ^ rr) << 4);

            uint32_t a[4][4];
            #pragma unroll
            for (int mi = 0; mi < 4; mi++)
                LDSM4(a[mi][0], a[mi][1], a[mi][2], a[mi][3], S + aAddr[mi] + cA);

            uint32_t b[2][4];
            #pragma unroll
            for (int p = 0; p < 2; p++)
                LDSM4(b[p][0], b[p][1], b[p][2], b[p][3], S + bAddr[p] + cB);

            #pragma unroll
            for (int mi = 0; mi < 4; mi++)
                #pragma unroll
                for (int ni = 0; ni < 4; ni++) {
                    uint32_t bb[2] = { b[ni >> 1][(ni & 1) * 2],
                                       b[ni >> 1][(ni & 1) * 2 + 1] };
                    mma16816(acc[mi][ni], a[mi], bb);
                }
        }
    }

    // ---- epilogue ----
    const size_t row0 = bm + m0 + q;
    const int    col0 = (int)bn + n0 + 2 * j;

    #pragma unroll
    for (int ni = 0; ni < 4; ni++) {
        const int col = col0 + 8 * ni;
        float bv0 = 0.f, bv1 = 0.f;
        if (EPI == 1) { bv0 = __ldg(bias + col); bv1 = __ldg(bias + col + 1); }
        #pragma unroll
        for (int mi = 0; mi < 4; mi++) {
            const size_t r = row0 + 16 * mi;
            if (EPI == 1) {
                __half* Ch = (__half*)Cv;
                *(half2*)(Ch + r * Nc + col) =
                    __floats2half2_rn(gelu_f(acc[mi][ni][0] + bv0),
                                      gelu_f(acc[mi][ni][1] + bv1));
                *(half2*)(Ch + (r + 8) * Nc + col) =
                    __floats2half2_rn(gelu_f(acc[mi][ni][2] + bv0),
                                      gelu_f(acc[mi][ni][3] + bv1));
            } else {
                float* Cf = (float*)Cv;
                float2 o0 = *(const float2*)(Cf + r * Nc + col);
                float2 o1 = *(const float2*)(Cf + (r + 8) * Nc + col);
                o0.x += acc[mi][ni][0];  o0.y += acc[mi][ni][1];
                o1.x += acc[mi][ni][2];  o1.y += acc[mi][ni][3];
                *(float2*)(Cf + r * Nc + col) = o0;
                *(float2*)(Cf + (r + 8) * Nc + col) = o1;
            }
        }
    }
}

// ---------------------------------------------------------------------------
// Paired block-wide sum over 256 threads: reduces (a,b) together
// ---------------------------------------------------------------------------
__device__ __forceinline__ float2 blk_sum2(float a, float b, float2* sbuf2) {
    #pragma unroll
    for (int o = 16; o > 0; o >>= 1) {
        a += __shfl_xor_sync(0xffffffffu, a, o);
        b += __shfl_xor_sync(0xffffffffu, b, o);
    }
    const int w = threadIdx.x >> 5;
    if ((threadIdx.x & 31) == 0) sbuf2[w] = make_float2(a, b);
    __syncthreads();
    if (threadIdx.x < 32) {
        float xa = 0.f, xb = 0.f;
        if (threadIdx.x < 8) { float2 v = sbuf2[threadIdx.x]; xa = v.x; xb = v.y; }
        #pragma unroll
        for (int o = 4; o > 0; o >>= 1) {
            xa += __shfl_xor_sync(0xffffffffu, xa, o);
            xb += __shfl_xor_sync(0xffffffffu, xb, o);
        }
        if (threadIdx.x == 0) sbuf2[0] = make_float2(xa, xb);
    }
    __syncthreads();
    float2 r = sbuf2[0];
    __syncthreads();
    return r;
}

// ---------------------------------------------------------------------------
// Fused pre-kernel:
//  blocks [0, TW1_BLKS)               : w1 (D x H) -> w1t (H x D) half
//  blocks [TW1_BLKS, PRE_TBLKS)       : w2 (H x D) -> w2t (D x H) half
//  blocks [PRE_TBLKS, PRE_TBLKS+NB)   : per-token LN1 + router + LN2 + gather
// Token path stages the 8 LUT rows (32 KB) into smem with cp.async issued
// BEFORE the LN chain, so the gather DRAM latency overlaps the reductions
// at zero register cost.
// ---------------------------------------------------------------------------
__global__ __launch_bounds__(256) void pre_kernel(
    const float* __restrict__ x, const int* __restrict__ ids,
    const float* __restrict__ lut,
    const float* __restrict__ ln1g, const float* __restrict__ ln1b,
    const float* __restrict__ ln2g, const float* __restrict__ ln2b,
    const float* __restrict__ rw,  const float* __restrict__ rb,
    const float* __restrict__ bias2,
    const float* __restrict__ w1,  const float* __restrict__ w2,
    float* __restrict__ out)
{
    __shared__ __align__(16) float s_lut[EE * DD];   // 32 KB gather staging
    __shared__ float tile[32][33];                   // transpose path
    __shared__ float2 sbuf2[8];                      // token path
    __shared__ float rp[EE * 8];
    __shared__ float slog[EE];
    __shared__ float s_h[DD];

    const int bid = blockIdx.x;
    const int tid = threadIdx.x;

    if (bid < PRE_TBLKS) {
        // ---------------- transpose path ----------------
        const float* in;  __half* o;  int rows, cols, bx, by;
        if (bid < TW1_BLKS) {
            in = w1; o = g_w1t; rows = DD; cols = HH;      // grid 128 x 32
            bx = bid & 127;  by = bid >> 7;
        } else {
            const int i2 = bid - TW1_BLKS;
            in = w2; o = g_w2t; rows = HH; cols = DD;      // grid 32 x 128
            bx = i2 & 31;    by = i2 >> 5;
        }
        const int tx = tid & 31, ty = tid >> 5;            // 32 x 8
        int xx = bx * 32 + tx;
        int yy = by * 32 + ty;
        #pragma unroll
        for (int jj = 0; jj < 32; jj += 8)
            tile[ty + jj][tx] = in[(size_t)(yy + jj) * cols + xx];
        __syncthreads();
        xx = by * 32 + tx;
        yy = bx * 32 + ty;
        #pragma unroll
        for (int jj = 0; jj < 32; jj += 8)
            o[(size_t)(yy + jj) * rows + xx] = __float2half(tile[tx][ty + jj]);
        return;
    }

    // ---------------- token path ----------------
    const int t = bid - PRE_TBLKS;

    // kick off the LUT gather into smem before any reduction work
    const int sid = __ldg(ids + t);
    const float* lbase = lut + (size_t)sid * (size_t)(EE * DD);
    const uint32_t slut = smem_u32(s_lut);
    #pragma unroll
    for (int e = 0; e < EE; e++)
        CP_ASYNC16(slut + (uint32_t)(e * DD + tid * 4) * 4,
                   lbase + (size_t)e * DD + tid * 4);
    CP_COMMIT();

    const float4 xv = ((const float4*)(x + (size_t)t * DD))[tid];

    float s1 = xv.x + xv.y + xv.z + xv.w;
    float s2 = xv.x*xv.x + xv.y*xv.y + xv.z*xv.z + xv.w*xv.w;
    const float2 m1 = blk_sum2(s1, s2, sbuf2);
    const float mu   = m1.x * (1.0f / DD);
    const float var  = m1.y * (1.0f / DD) - mu * mu;
    const float rstd = rsqrtf(var + 1e-5f);

    float4 g1 = ((const float4*)ln1g)[tid];
    float4 c1 = ((const float4*)ln1b)[tid];
    float h[4];
    h[0] = (xv.x - mu) * rstd * g1.x + c1.x;
    h[1] = (xv.y - mu) * rstd * g1.y + c1.y;
    h[2] = (xv.z - mu) * rstd * g1.z + c1.z;
    h[3] = (xv.w - mu) * rstd * g1.w + c1.w;

    // stash h in smem for the coalesced router pass
    ((float4*)s_h)[tid] = make_float4(h[0], h[1], h[2], h[3]);
    __syncthreads();

    // router partials: d = tid + 256*jj -> warp-coalesced rw reads
    float p[EE];
    #pragma unroll
    for (int e = 0; e < EE; e++) p[e] = 0.0f;
    #pragma unroll
    for (int jj = 0; jj < 4; jj++) {
        const int d = tid + 256 * jj;
        const float hd = s_h[d];
        const float4* row = (const float4*)(rw + (size_t)d * EE);
        const float4 r0 = row[0], r1 = row[1];
        p[0] += hd * r0.x;  p[1] += hd * r0.y;
        p[2] += hd * r0.z;  p[3] += hd * r0.w;
        p[4] += hd * r1.x;  p[5] += hd * r1.y;
        p[6] += hd * r1.z;  p[7] += hd * r1.w;
    }
    #pragma unroll
    for (int e = 0; e < EE; e++) {
        float v = p[e];
        #pragma unroll
        for (int o = 16; o > 0; o >>= 1) v += __shfl_xor_sync(0xffffffffu, v, o);
        if ((tid & 31) == 0) rp[e * 8 + (tid >> 5)] = v;
    }
    __syncthreads();
    if (tid < EE) {
        float v = rb[tid];
        #pragma unroll
        for (int w = 0; w < 8; w++) v += rp[tid * 8 + w];
        slog[tid] = v;
    }
    __syncthreads();

    float r[EE];
    float mx = -1e30f;
    #pragma unroll
    for (int e = 0; e < EE; e++) mx = fmaxf(mx, slog[e]);
    float den = 0.0f;
    #pragma unroll
    for (int e = 0; e < EE; e++) { r[e] = __expf(slog[e] - mx); den += r[e]; }
    const float inv = 1.0f / den;
    #pragma unroll
    for (int e = 0; e < EE; e++) r[e] *= inv;

    float t1 = h[0] + h[1] + h[2] + h[3];
    float t2 = h[0]*h[0] + h[1]*h[1] + h[2]*h[2] + h[3]*h[3];
    const float2 m2 = blk_sum2(t1, t2, sbuf2);
    const float mu2   = m2.x * (1.0f / DD);
    const float var2  = m2.y * (1.0f / DD) - mu2 * mu2;
    const float rstd2 = rsqrtf(var2 + 1e-5f);

    float4 g2 = ((const float4*)ln2g)[tid];
    float4 c2 = ((const float4*)ln2b)[tid];
    half2* h2p = (half2*)(g_h2 + (size_t)t * DD);
    h2p[tid * 2]     = __floats2half2_rn((h[0] - mu2) * rstd2 * g2.x + c2.x,
                                         (h[1] - mu2) * rstd2 * g2.y + c2.y);
    h2p[tid * 2 + 1] = __floats2half2_rn((h[2] - mu2) * rstd2 * g2.z + c2.z,
                                         (h[3] - mu2) * rstd2 * g2.w + c2.w);

    // gather staged in smem: combine with softmax weights
    CP_WAIT(0);
    __syncthreads();

    float4 acc = make_float4(0.f, 0.f, 0.f, 0.f);
    #pragma unroll
    for (int e = 0; e < EE; e++) {
        const float4 lv = ((const float4*)s_lut)[e * (DD / 4) + tid];
        acc.x += r[e] * lv.x;  acc.y += r[e] * lv.y;
        acc.z += r[e] * lv.z;  acc.w += r[e] * lv.w;
    }

    float4 b2v = ((const float4*)bias2)[tid];
    float4 o;
    o.x = xv.x + acc.x + b2v.x;
    o.y = xv.y + acc.y + b2v.y;
    o.z = xv.z + acc.z + b2v.z;
    o.w = xv.w + acc.w + b2v.w;
    ((float4*)(out + (size_t)t * DD))[tid] = o;
}

// ---------------------------------------------------------------------------
// launch
// ---------------------------------------------------------------------------
extern "C" void kernel_launch(void* const* d_in, const int* in_sizes, int n_in,
                              void* d_out, int out_size)
{
    const float* x    = (const float*)d_in[0];
    const int*   ids  = (const int*)  d_in[1];
    const float* lut  = (const float*)d_in[2];
    const float* ln1g = (const float*)d_in[3];
    const float* ln1b = (const float*)d_in[4];
    const float* ln2g = (const float*)d_in[5];
    const float* ln2b = (const float*)d_in[6];
    const float* rw   = (const float*)d_in[7];
    const float* rb   = (const float*)d_in[8];
    const float* w1   = (const float*)d_in[9];
    const float* b1   = (const float*)d_in[10];
    const float* w2   = (const float*)d_in[11];
    const float* b2   = (const float*)d_in[12];
    float* out = (float*)d_out;

    cudaFuncSetAttribute(mma_gemm<DD, HH, 1>, cudaFuncAttributeMaxDynamicSharedMemorySize, SMEM_DYN);
    cudaFuncSetAttribute(mma_gemm<HH, DD, 2>, cudaFuncAttributeMaxDynamicSharedMemorySize, SMEM_DYN);

    __half* w1t; cudaGetSymbolAddress((void**)&w1t, g_w1t);
    __half* w2t; cudaGetSymbolAddress((void**)&w2t, g_w2t);
    __half* h2;  cudaGetSymbolAddress((void**)&h2,  g_h2);
    __half* act; cudaGetSymbolAddress((void**)&act, g_act);

    // fused: weight transposes + token-wise LN/router/gather (cp.async staged)
    pre_kernel<<<PRE_TBLKS + NB, 256>>>(
        x, ids, lut, ln1g, ln1b, ln2g, ln2b, rw, rb, b2, w1, w2, out);

    // act = gelu(h2 @ w1 + b1)   [8192 x 4096], K=1024  (half in, half out)
    mma_gemm<DD, HH, 1><<<dim3(HH / BN, NB / BM), 256, SMEM_DYN>>>(h2, w1t, b1, act);

    // out += act @ w2            [8192 x 1024], K=4096  (half in, f32 +=)
    mma_gemm<HH, DD, 2><<<dim3(DD / BN, NB / BM), 256, SMEM_DYN>>>(act, w2t, nullptr, out);
}

// round 15
// speedup vs baseline: 1.0481x; 1.0352x over previous
#include <cuda_runtime.h>
#include <cuda_fp16.h>
#include <math.h>
#include <stdint.h>

// Problem constants
#define NB   8192      // B*S tokens (4*2048)
#define DD   1024      // n_embd
#define EE   8         // experts
#define HH   4096      // MLP hidden

// GEMM tiling: CTA 128(M) x 128(N), 8 warps of 64x32, BK=64 halves, 3 stages
#define BM 128
#define BN 128
#define BKH 64                              // halves per stage row (128 B)
#define A_BYTES (BM * BKH * 2)              // 16 KB
#define B_BYTES (BN * BKH * 2)              // 16 KB
#define STAGE_BYTES (A_BYTES + B_BYTES)     // 32 KB
#define NSTAGE 3
#define SMEM_DYN (NSTAGE * STAGE_BYTES)     // 96 KB  -> 2 CTAs/SM

// fused GEMM kernel: first G1_BLKS CTAs = GEMM1, rest = GEMM2
#define G1_NB (HH / BN)                     // 32
#define G1_MB (NB / BM)                     // 64
#define G1_BLKS (G1_NB * G1_MB)             // 2048
#define G2_NB (DD / BN)                     // 8
#define G2_MB (NB / BM)                     // 64
#define G2_BLKS (G2_NB * G2_MB)             // 512

// pre-kernel block partitions
#define TW1_BLKS 4096
#define TW2_BLKS 4096
#define PRE_TBLKS (TW1_BLKS + TW2_BLKS)

// Scratch (static device globals -- no runtime allocation)
__device__ __half g_h2 [(size_t)NB * DD];   // 16 MB : LN2 output (half)
__device__ __half g_act[(size_t)NB * HH];   // 64 MB : gelu(h2@w1+b1) (half)
__device__ __half g_w1t[(size_t)HH * DD];   // 8 MB  : w1^T (H x D) K-major half
__device__ __half g_w2t[(size_t)DD * HH];   // 8 MB  : w2^T (D x H) K-major half
__device__ int    g_cnt[G1_MB];             // per-M-group completion counters

// ---------------------------------------------------------------------------
// helpers
// ---------------------------------------------------------------------------
__device__ __forceinline__ uint32_t smem_u32(const void* p) {
    uint32_t a;
    asm("{ .reg .u64 t; cvta.to.shared.u64 t, %1; cvt.u32.u64 %0, t; }" : "=r"(a) : "l"(p));
    return a;
}
#define CP_ASYNC16(dst, src) \
    asm volatile("cp.async.cg.shared.global [%0], [%1], 16;" :: "r"(dst), "l"(src))
#define CP_COMMIT() asm volatile("cp.async.commit_group;" ::: "memory")
#define CP_WAIT(n)  asm volatile("cp.async.wait_group %0;" :: "n"(n) : "memory")

#define LDSM4(d0, d1, d2, d3, addr) \
    asm volatile("ldmatrix.sync.aligned.m8n8.x4.shared.b16 {%0,%1,%2,%3}, [%4];" \
        : "=r"(d0), "=r"(d1), "=r"(d2), "=r"(d3) : "r"(addr))

__device__ __forceinline__ void mma16816(float* d, const uint32_t* a, const uint32_t* b) {
    asm volatile(
        "mma.sync.aligned.m16n8k16.row.col.f32.f16.f16.f32 "
        "{%0,%1,%2,%3}, {%4,%5,%6,%7}, {%8,%9}, {%0,%1,%2,%3};"
        : "+f"(d[0]), "+f"(d[1]), "+f"(d[2]), "+f"(d[3])
        : "r"(a[0]), "r"(a[1]), "r"(a[2]), "r"(a[3]), "r"(b[0]), "r"(b[1]));
}

__device__ __forceinline__ float gelu_f(float v) {
    const float c = 0.7978845608028654f;
    float u = c * (v + 0.044715f * v * v * v);
    return 0.5f * v * (1.0f + tanhf(u));
}

// ---------------------------------------------------------------------------
// Stage copy: ROWS rows x 64 halves (128B/row = 8 chunks of 16B), gmem row
// stride ldg halves, XOR-swizzled (chunk c -> c ^ (row & 7)). 256 threads.
// ---------------------------------------------------------------------------
template<int ROWS>
__device__ __forceinline__ void stage_copy(const __half* __restrict__ g, int ldg,
                                           uint32_t sbase, int tid) {
    #pragma unroll
    for (int p = 0; p < ROWS * 8 / 256; p++) {
        const int idx = tid + p * 256;
        const int row = idx >> 3;
        const int c   = idx & 7;
        const uint32_t dst = sbase + (uint32_t)row * 128 + (uint32_t)((c ^ (row & 7)) << 4);
        CP_ASYNC16(dst, (const char*)g + (size_t)row * ldg * 2 + (size_t)c * 16);
    }
}

// ---------------------------------------------------------------------------
// GEMM body: C[M x Nc] (+)= A[M x Kc] * Bt[N x Kc]^T   (A,Bt half)
// 8 warps, warp tile 64x32, arrangement 2Mx4N.
// EPI=1: C(half) = gelu(acc + bias[n])   EPI=2: C(float) += acc
// ---------------------------------------------------------------------------
template<int Kc, int Nc, int EPI>
__device__ __forceinline__ void gemm_body(
    const __half* __restrict__ A, const __half* __restrict__ Bt,
    const float* __restrict__ bias, void* __restrict__ Cv,
    size_t bm, size_t bn, char* sm, int tid)
{
    const int wid = tid >> 5;
    const int lid = tid & 31;
    const int q   = lid >> 2;
    const int j   = lid & 3;
    const int m0  = (wid >> 2) * 64;
    const int n0  = (wid & 3) * 32;

    const __half* Ab = A  + bm * Kc;
    const __half* Bb = Bt + bn * Kc;

    const uint32_t sb0 = smem_u32(sm);
    const int KT = Kc / BKH;

    const int seg = lid >> 3;
    const int rr  = lid & 7;
    const int khA = seg >> 1;
    const int khB = seg & 1;
    uint32_t aAddr[4], bAddr[2];
    #pragma unroll
    for (int mi = 0; mi < 4; mi++)
        aAddr[mi] = (uint32_t)(m0 + mi * 16 + (seg & 1) * 8 + rr) * 128;
    #pragma unroll
    for (int p = 0; p < 2; p++)
        bAddr[p] = (uint32_t)A_BYTES + (uint32_t)(n0 + p * 16 + (seg >> 1) * 8 + rr) * 128;

    float acc[4][4][4];
    #pragma unroll
    for (int mi = 0; mi < 4; mi++)
        #pragma unroll
        for (int ni = 0; ni < 4; ni++)
            #pragma unroll
            for (int v = 0; v < 4; v++) acc[mi][ni][v] = 0.0f;

    #pragma unroll
    for (int s = 0; s < NSTAGE - 1; s++) {
        const uint32_t sa = sb0 + (uint32_t)s * STAGE_BYTES;
        stage_copy<BM>(Ab + (size_t)s * BKH, Kc, sa, tid);
        stage_copy<BN>(Bb + (size_t)s * BKH, Kc, sa + A_BYTES, tid);
        CP_COMMIT();
    }

    for (int kt = 0; kt < KT; kt++) {
        CP_WAIT(NSTAGE - 2);
        __syncthreads();

        if (kt + NSTAGE - 1 < KT) {
            const uint32_t sa = sb0 + (uint32_t)((kt + NSTAGE - 1) % NSTAGE) * STAGE_BYTES;
            stage_copy<BM>(Ab + (size_t)(kt + NSTAGE - 1) * BKH, Kc, sa, tid);
            stage_copy<BN>(Bb + (size_t)(kt + NSTAGE - 1) * BKH, Kc, sa + A_BYTES, tid);
        }
        CP_COMMIT();

        const uint32_t S = sb0 + (uint32_t)(kt % NSTAGE) * STAGE_BYTES;

        #pragma unroll
        for (int ks = 0; ks < BKH / 16; ks++) {
            const uint32_t cA = (uint32_t)(((2 * ks + khA) ^ rr) << 4);
            const uint32_t cB = (uint32_t)(((2 * ks + khB) ^ rr) << 4);

            uint32_t a[4][4];
            #pragma unroll
            for (int mi = 0; mi < 4; mi++)
                LDSM4(a[mi][0], a[mi][1], a[mi][2], a[mi][3], S + aAddr[mi] + cA);

            uint32_t b[2][4];
            #pragma unroll
            for (int p = 0; p < 2; p++)
                LDSM4(b[p][0], b[p][1], b[p][2], b[p][3], S + bAddr[p] + cB);

            #pragma unroll
            for (int mi = 0; mi < 4; mi++)
                #pragma unroll
                for (int ni = 0; ni < 4; ni++) {
                    uint32_t bb[2] = { b[ni >> 1][(ni & 1) * 2],
                                       b[ni >> 1][(ni & 1) * 2 + 1] };
                    mma16816(acc[mi][ni], a[mi], bb);
                }
        }
    }

    const size_t row0 = bm + m0 + q;
    const int    col0 = (int)bn + n0 + 2 * j;

    #pragma unroll
    for (int ni = 0; ni < 4; ni++) {
        const int col = col0 + 8 * ni;
        float bv0 = 0.f, bv1 = 0.f;
        if (EPI == 1) { bv0 = __ldg(bias + col); bv1 = __ldg(bias + col + 1); }
        #pragma unroll
        for (int mi = 0; mi < 4; mi++) {
            const size_t r = row0 + 16 * mi;
            if (EPI == 1) {
                __half* Ch = (__half*)Cv;
                *(half2*)(Ch + r * Nc + col) =
                    __floats2half2_rn(gelu_f(acc[mi][ni][0] + bv0),
                                      gelu_f(acc[mi][ni][1] + bv1));
                *(half2*)(Ch + (r + 8) * Nc + col) =
                    __floats2half2_rn(gelu_f(acc[mi][ni][2] + bv0),
                                      gelu_f(acc[mi][ni][3] + bv1));
            } else {
                float* Cf = (float*)Cv;
                float2 o0 = *(const float2*)(Cf + r * Nc + col);
                float2 o1 = *(const float2*)(Cf + (r + 8) * Nc + col);
                o0.x += acc[mi][ni][0];  o0.y += acc[mi][ni][1];
                o1.x += acc[mi][ni][2];  o1.y += acc[mi][ni][3];
                *(float2*)(Cf + r * Nc + col) = o0;
                *(float2*)(Cf + (r + 8) * Nc + col) = o1;
            }
        }
    }
}

// ---------------------------------------------------------------------------
// Fused GEMM kernel:
//  bids [0, G1_BLKS)            : GEMM1  act = gelu(h2 @ w1 + b1)
//  bids [G1_BLKS, +G2_BLKS)     : GEMM2  out += act @ w2   (waits on g_cnt)
// GEMM1 bids grouped by M so an M-group's 32 producers are contiguous.
// ---------------------------------------------------------------------------
__global__ __launch_bounds__(256, 2) void fused_gemm(
    const __half* __restrict__ h2, const __half* __restrict__ w1t,
    const float* __restrict__ b1,  __half* __restrict__ act,
    const __half* __restrict__ w2t, float* __restrict__ out)
{
    extern __shared__ __align__(16) char sm[];
    const int tid = threadIdx.x;
    const int bid = blockIdx.x;

    if (bid < G1_BLKS) {
        const int bn_i = bid & (G1_NB - 1);
        const int bm_i = bid >> 5;                 // log2(G1_NB)=5
        gemm_body<DD, HH, 1>(h2, w1t, b1, act,
                             (size_t)bm_i * BM, (size_t)bn_i * BN, sm, tid);
        __syncthreads();
        __threadfence();
        if (tid == 0) atomicAdd(&g_cnt[bm_i], 1);
    } else {
        const int b2 = bid - G1_BLKS;
        const int bn_i = b2 & (G2_NB - 1);
        const int bm_i = b2 >> 3;                  // log2(G2_NB)=3
        if (tid == 0) {
            while (*(volatile int*)&g_cnt[bm_i] != G1_NB) { }
        }
        __syncthreads();
        __threadfence();
        gemm_body<HH, DD, 2>(act, w2t, nullptr, out,
                             (size_t)bm_i * BM, (size_t)bn_i * BN, sm, tid);
    }
}

// ---------------------------------------------------------------------------
// Paired block-wide sum over 256 threads: reduces (a,b) together
// ---------------------------------------------------------------------------
__device__ __forceinline__ float2 blk_sum2(float a, float b, float2* sbuf2) {
    #pragma unroll
    for (int o = 16; o > 0; o >>= 1) {
        a += __shfl_xor_sync(0xffffffffu, a, o);
        b += __shfl_xor_sync(0xffffffffu, b, o);
    }
    const int w = threadIdx.x >> 5;
    if ((threadIdx.x & 31) == 0) sbuf2[w] = make_float2(a, b);
    __syncthreads();
    if (threadIdx.x < 32) {
        float xa = 0.f, xb = 0.f;
        if (threadIdx.x < 8) { float2 v = sbuf2[threadIdx.x]; xa = v.x; xb = v.y; }
        #pragma unroll
        for (int o = 4; o > 0; o >>= 1) {
            xa += __shfl_xor_sync(0xffffffffu, xa, o);
            xb += __shfl_xor_sync(0xffffffffu, xb, o);
        }
        if (threadIdx.x == 0) sbuf2[0] = make_float2(xa, xb);
    }
    __syncthreads();
    float2 r = sbuf2[0];
    __syncthreads();
    return r;
}

// ---------------------------------------------------------------------------
// Fused pre-kernel (transposes + token work + counter reset)
// ---------------------------------------------------------------------------
__global__ __launch_bounds__(256) void pre_kernel(
    const float* __restrict__ x, const int* __restrict__ ids,
    const float* __restrict__ lut,
    const float* __restrict__ ln1g, const float* __restrict__ ln1b,
    const float* __restrict__ ln2g, const float* __restrict__ ln2b,
    const float* __restrict__ rw,  const float* __restrict__ rb,
    const float* __restrict__ bias2,
    const float* __restrict__ w1,  const float* __restrict__ w2,
    float* __restrict__ out)
{
    __shared__ __align__(16) float s_lut[EE * DD];   // 32 KB gather staging
    __shared__ float tile[32][33];                   // transpose path
    __shared__ float2 sbuf2[8];                      // token path
    __shared__ float rp[EE * 8];
    __shared__ float slog[EE];
    __shared__ float s_h[DD];

    const int bid = blockIdx.x;
    const int tid = threadIdx.x;

    if (bid < PRE_TBLKS) {
        // reset GEMM dependency counters (block 0 only)
        if (bid == 0 && tid < G1_MB) g_cnt[tid] = 0;

        // ---------------- transpose path ----------------
        const float* in;  __half* o;  int rows, cols, bx, by;
        if (bid < TW1_BLKS) {
            in = w1; o = g_w1t; rows = DD; cols = HH;
            bx = bid & 127;  by = bid >> 7;
        } else {
            const int i2 = bid - TW1_BLKS;
            in = w2; o = g_w2t; rows = HH; cols = DD;
            bx = i2 & 31;    by = i2 >> 5;
        }
        const int tx = tid & 31, ty = tid >> 5;
        int xx = bx * 32 + tx;
        int yy = by * 32 + ty;
        #pragma unroll
        for (int jj = 0; jj < 32; jj += 8)
            tile[ty + jj][tx] = in[(size_t)(yy + jj) * cols + xx];
        __syncthreads();
        xx = by * 32 + tx;
        yy = bx * 32 + ty;
        #pragma unroll
        for (int jj = 0; jj < 32; jj += 8)
            o[(size_t)(yy + jj) * rows + xx] = __float2half(tile[tx][ty + jj]);
        return;
    }

    // ---------------- token path ----------------
    const int t = bid - PRE_TBLKS;

    // kick off the LUT gather into smem before any reduction work
    const int sid = __ldg(ids + t);
    const float* lbase = lut + (size_t)sid * (size_t)(EE * DD);
    const uint32_t slut = smem_u32(s_lut);
    #pragma unroll
    for (int e = 0; e < EE; e++)
        CP_ASYNC16(slut + (uint32_t)(e * DD + tid * 4) * 4,
                   lbase + (size_t)e * DD + tid * 4);
    CP_COMMIT();

    const float4 xv = ((const float4*)(x + (size_t)t * DD))[tid];

    float s1 = xv.x + xv.y + xv.z + xv.w;
    float s2 = xv.x*xv.x + xv.y*xv.y + xv.z*xv.z + xv.w*xv.w;
    const float2 m1 = blk_sum2(s1, s2, sbuf2);
    const float mu   = m1.x * (1.0f / DD);
    const float var  = m1.y * (1.0f / DD) - mu * mu;
    const float rstd = rsqrtf(var + 1e-5f);

    float4 g1 = ((const float4*)ln1g)[tid];
    float4 c1 = ((const float4*)ln1b)[tid];
    float h[4];
    h[0] = (xv.x - mu) * rstd * g1.x + c1.x;
    h[1] = (xv.y - mu) * rstd * g1.y + c1.y;
    h[2] = (xv.z - mu) * rstd * g1.z + c1.z;
    h[3] = (xv.w - mu) * rstd * g1.w + c1.w;

    ((float4*)s_h)[tid] = make_float4(h[0], h[1], h[2], h[3]);
    __syncthreads();

    float p[EE];
    #pragma unroll
    for (int e = 0; e < EE; e++) p[e] = 0.0f;
    #pragma unroll
    for (int jj = 0; jj < 4; jj++) {
        const int d = tid + 256 * jj;
        const float hd = s_h[d];
        const float4* row = (const float4*)(rw + (size_t)d * EE);
        const float4 r0 = row[0], r1 = row[1];
        p[0] += hd * r0.x;  p[1] += hd * r0.y;
        p[2] += hd * r0.z;  p[3] += hd * r0.w;
        p[4] += hd * r1.x;  p[5] += hd * r1.y;
        p[6] += hd * r1.z;  p[7] += hd * r1.w;
    }
    #pragma unroll
    for (int e = 0; e < EE; e++) {
        float v = p[e];
        #pragma unroll
        for (int o = 16; o > 0; o >>= 1) v += __shfl_xor_sync(0xffffffffu, v, o);
        if ((tid & 31) == 0) rp[e * 8 + (tid >> 5)] = v;
    }
    __syncthreads();
    if (tid < EE) {
        float v = rb[tid];
        #pragma unroll
        for (int w = 0; w < 8; w++) v += rp[tid * 8 + w];
        slog[tid] = v;
    }
    __syncthreads();

    float r[EE];
    float mx = -1e30f;
    #pragma unroll
    for (int e = 0; e < EE; e++) mx = fmaxf(mx, slog[e]);
    float den = 0.0f;
    #pragma unroll
    for (int e = 0; e < EE; e++) { r[e] = __expf(slog[e] - mx); den += r[e]; }
    const float inv = 1.0f / den;
    #pragma unroll
    for (int e = 0; e < EE; e++) r[e] *= inv;

    float t1 = h[0] + h[1] + h[2] + h[3];
    float t2 = h[0]*h[0] + h[1]*h[1] + h[2]*h[2] + h[3]*h[3];
    const float2 m2 = blk_sum2(t1, t2, sbuf2);
    const float mu2   = m2.x * (1.0f / DD);
    const float var2  = m2.y * (1.0f / DD) - mu2 * mu2;
    const float rstd2 = rsqrtf(var2 + 1e-5f);

    float4 g2 = ((const float4*)ln2g)[tid];
    float4 c2 = ((const float4*)ln2b)[tid];
    half2* h2p = (half2*)(g_h2 + (size_t)t * DD);
    h2p[tid * 2]     = __floats2half2_rn((h[0] - mu2) * rstd2 * g2.x + c2.x,
                                         (h[1] - mu2) * rstd2 * g2.y + c2.y);
    h2p[tid * 2 + 1] = __floats2half2_rn((h[2] - mu2) * rstd2 * g2.z + c2.z,
                                         (h[3] - mu2) * rstd2 * g2.w + c2.w);

    CP_WAIT(0);
    __syncthreads();

    float4 acc = make_float4(0.f, 0.f, 0.f, 0.f);
    #pragma unroll
    for (int e = 0; e < EE; e++) {
        const float4 lv = ((const float4*)s_lut)[e * (DD / 4) + tid];
        acc.x += r[e] * lv.x;  acc.y += r[e] * lv.y;
        acc.z += r[e] * lv.z;  acc.w += r[e] * lv.w;
    }

    float4 b2v = ((const float4*)bias2)[tid];
    float4 o;
    o.x = xv.x + acc.x + b2v.x;
    o.y = xv.y + acc.y + b2v.y;
    o.z = xv.z + acc.z + b2v.z;
    o.w = xv.w + acc.w + b2v.w;
    ((float4*)(out + (size_t)t * DD))[tid] = o;
}

// ---------------------------------------------------------------------------
// launch
// ---------------------------------------------------------------------------
extern "C" void kernel_launch(void* const* d_in, const int* in_sizes, int n_in,
                              void* d_out, int out_size)
{
    const float* x    = (const float*)d_in[0];
    const int*   ids  = (const int*)  d_in[1];
    const float* lut  = (const float*)d_in[2];
    const float* ln1g = (const float*)d_in[3];
    const float* ln1b = (const float*)d_in[4];
    const float* ln2g = (const float*)d_in[5];
    const float* ln2b = (const float*)d_in[6];
    const float* rw   = (const float*)d_in[7];
    const float* rb   = (const float*)d_in[8];
    const float* w1   = (const float*)d_in[9];
    const float* b1   = (const float*)d_in[10];
    const float* w2   = (const float*)d_in[11];
    const float* b2   = (const float*)d_in[12];
    float* out = (float*)d_out;

    cudaFuncSetAttribute(fused_gemm, cudaFuncAttributeMaxDynamicSharedMemorySize, SMEM_DYN);

    __half* w1t; cudaGetSymbolAddress((void**)&w1t, g_w1t);
    __half* w2t; cudaGetSymbolAddress((void**)&w2t, g_w2t);
    __half* h2;  cudaGetSymbolAddress((void**)&h2,  g_h2);
    __half* act; cudaGetSymbolAddress((void**)&act, g_act);

    // fused: counter reset + weight transposes + token work (cp.async staged)
    pre_kernel<<<PRE_TBLKS + NB, 256>>>(
        x, ids, lut, ln1g, ln1b, ln2g, ln2b, rw, rb, b2, w1, w2, out);

    // fused GEMM1 + GEMM2 with flag-based dependency
    fused_gemm<<<G1_BLKS + G2_BLKS, 256, SMEM_DYN>>>(h2, w1t, b1, act, w2t, out);
}